// round 4
// baseline (speedup 1.0000x reference)
#include <cuda_runtime.h>

// Problem constants
#define BATCH 32
#define SEQ   2048
#define NPOS  (BATCH * SEQ)   // 65536 positions
#define M     10              // number of primes
#define NTAB  129             // sum of primes 2+3+5+7+11+13+17+19+23+29

// Tables (filled every launch by init kernel; deterministic, graph-capturable)
// g_tabW: { K*cos, K*cos, K*sin, K*sin }  with K = TEMP * log2(e)  (softmax logits in log2 domain)
// g_tabE: { cos, sin }                    (re-encode templates)
__device__ float4 g_tabW[NTAB];
__device__ float2 g_tabE[NTAB];

__global__ void init_tables_kernel() {
    int idx = threadIdx.x;
    if (idx >= NTAB) return;
    const int primes[M] = {2, 3, 5, 7, 11, 13, 17, 19, 23, 29};
    int k = idx, p = 29;
    for (int pi = 0; pi < M; pi++) {
        if (k < primes[pi]) { p = primes[pi]; break; }
        k -= primes[pi];
    }
    double ang = 6.283185307179586476925287 * (double)k / (double)p;
    float c = (float)cos(ang), s = (float)sin(ang);  // matches numpy f64->f32 rounding
    const double K = 1000.0 * 1.4426950408889634074; // TEMP * log2(e)
    float cK = (float)((double)c * K);
    float sK = (float)((double)s * K);
    g_tabW[idx] = make_float4(cK, cK, sK, sK);
    g_tabE[idx] = make_float2(c, s);
}

// ---- packed f32x2 helpers (Blackwell FFMA2; only reachable via PTX) ----
union F2U { float2 f; unsigned long long u; };

__device__ __forceinline__ float2 f2fma(float2 a, float2 b, float2 c) {
    F2U A, B, C, D; A.f = a; B.f = b; C.f = c;
    asm("fma.rn.f32x2 %0, %1, %2, %3;" : "=l"(D.u) : "l"(A.u), "l"(B.u), "l"(C.u));
    return D.f;
}
__device__ __forceinline__ float2 f2mul(float2 a, float2 b) {
    F2U A, B, D; A.f = a; B.f = b;
    asm("mul.rn.f32x2 %0, %1, %2;" : "=l"(D.u) : "l"(A.u), "l"(B.u));
    return D.f;
}
__device__ __forceinline__ float2 f2add(float2 a, float2 b) {
    F2U A, B, D; A.f = a; B.f = b;
    asm("add.rn.f32x2 %0, %1, %2;" : "=l"(D.u) : "l"(A.u), "l"(B.u));
    return D.f;
}
__device__ __forceinline__ float ex2f(float x) {
    float r; asm("ex2.approx.f32 %0, %1;" : "=f"(r) : "f"(x)); return r;
}
__device__ __forceinline__ float rcpf(float x) {
    float r; asm("rcp.approx.f32 %0, %1;" : "=f"(r) : "f"(x)); return r;
}

__device__ __forceinline__ void emit_addsub(float2 A, float2 B, float2* oAdd, float2* oSub, int idx) {
    float t1 = A.x * B.x, t2 = A.y * B.y, t3 = A.y * B.x, t4 = A.x * B.y;
    oAdd[idx] = make_float2(t1 - t2, t3 + t4);
    oSub[idx] = make_float2(t1 + t2, t3 - t4);
}

// ---- packed-lane path (small/medium primes): a/b sides in the two f32x2 lanes ----
template <int P, int PI>
__device__ __forceinline__ void prime_packed(
    int pos, const float2* __restrict__ a2, const float2* __restrict__ b2,
    float2* __restrict__ oAdd, float2* __restrict__ oSub, float2* __restrict__ oMul,
    const float4* __restrict__ shW, const float2* __restrict__ shE)
{
    const int idx = pos * M + PI;
    const float2 A = a2[idx], B = b2[idx];
    emit_addsub(A, B, oAdd, oSub, idx);

    const float2 c2 = make_float2(A.x, B.x);
    const float2 s2 = make_float2(A.y, B.y);

    // logits in log2 domain (tables pre-scaled by TEMP*log2e)
    float2 w[P];
#pragma unroll
    for (int i = 0; i < P; i++) {
        float4 t = shW[i];
        w[i] = f2fma(c2, make_float2(t.x, t.y), f2mul(s2, make_float2(t.z, t.w)));
    }

    // dual-accumulator max per lane
    float a0 = w[0].x, b0 = w[0].y;
    float a1 = (P > 1) ? w[1].x : w[0].x;
    float b1 = (P > 1) ? w[1].y : w[0].y;
#pragma unroll
    for (int i = 2; i < P; i++) {
        if (i & 1) { a1 = fmaxf(a1, w[i].x); b1 = fmaxf(b1, w[i].y); }
        else       { a0 = fmaxf(a0, w[i].x); b0 = fmaxf(b0, w[i].y); }
    }
    const float2 nm = make_float2(-fmaxf(a0, a1), -fmaxf(b0, b1));

    // exp2 + packed sums, dual accumulators
    float2 s0 = make_float2(0.f, 0.f), s1 = make_float2(0.f, 0.f);
#pragma unroll
    for (int i = 0; i < P; i++) {
        float2 arg = f2add(w[i], nm);
        w[i] = make_float2(ex2f(arg.x), ex2f(arg.y));
        if (i & 1) s1 = f2add(s1, w[i]); else s0 = f2add(s0, w[i]);
    }
    const float2 S = f2add(s0, s1);
    const float Sa = S.x, Sb = S.y;

    // dist; residue-0 closed form for i=0 / j=0 cross terms
    float dist[P];
    dist[0] = fmaf(w[0].x, Sb, fmaf(w[0].y, Sa, -(w[0].x * w[0].y)));
#pragma unroll
    for (int k = 1; k < P; k++) dist[k] = 0.f;
#pragma unroll
    for (int i = 1; i < P; i++) {
        const float wai = w[i].x;
#pragma unroll
        for (int j = 1; j < P; j++) {
            const int k = (i * j) % P;   // bijection over 1..P-1 per i
            dist[k] = fmaf(wai, w[j].y, dist[k]);
        }
    }

    // re-encode + normalize
    float X0 = 0.f, X1 = 0.f, Y0 = 0.f, Y1 = 0.f;
#pragma unroll
    for (int k = 0; k < P; k++) {
        float2 e = shE[k];
        if (k & 1) { X1 = fmaf(dist[k], e.x, X1); Y1 = fmaf(dist[k], e.y, Y1); }
        else       { X0 = fmaf(dist[k], e.x, X0); Y0 = fmaf(dist[k], e.y, Y0); }
    }
    const float inv = rcpf(Sa * Sb);
    oMul[idx] = make_float2((X0 + X1) * inv, (Y0 + Y1) * inv);
}

// ---- low-register path (p=23, 29): store only wb; recompute wa per outer-i ----
template <int P, int PI>
__device__ __forceinline__ void prime_lowreg(
    int pos, const float2* __restrict__ a2, const float2* __restrict__ b2,
    float2* __restrict__ oAdd, float2* __restrict__ oSub, float2* __restrict__ oMul,
    const float4* __restrict__ shW, const float2* __restrict__ shE)
{
    const int idx = pos * M + PI;
    const float2 A = a2[idx], B = b2[idx];
    emit_addsub(A, B, oAdd, oSub, idx);

    const float2 c2 = make_float2(A.x, B.x);
    const float2 s2 = make_float2(A.y, B.y);

    // pass 1: packed logits, packed max (no storage)
    float a0, a1, b0, b1;
    {
        float4 t0 = shW[0];
        float2 l0 = f2fma(c2, make_float2(t0.x, t0.y), f2mul(s2, make_float2(t0.z, t0.w)));
        float4 t1 = shW[1];
        float2 l1 = f2fma(c2, make_float2(t1.x, t1.y), f2mul(s2, make_float2(t1.z, t1.w)));
        a0 = l0.x; b0 = l0.y; a1 = l1.x; b1 = l1.y;
    }
#pragma unroll
    for (int i = 2; i < P; i++) {
        float4 t = shW[i];
        float2 l = f2fma(c2, make_float2(t.x, t.y), f2mul(s2, make_float2(t.z, t.w)));
        if (i & 1) { a1 = fmaxf(a1, l.x); b1 = fmaxf(b1, l.y); }
        else       { a0 = fmaxf(a0, l.x); b0 = fmaxf(b0, l.y); }
    }
    const float mxa = fmaxf(a0, a1), mxb = fmaxf(b0, b1);
    const float2 nm = make_float2(-mxa, -mxb);

    // pass 2: recompute logits, exp; store wb only; sums for both sides
    float wb[P];
    float Sa = 0.f, Sb = 0.f, wa0 = 0.f;
#pragma unroll
    for (int i = 0; i < P; i++) {
        float4 t = shW[i];
        float2 l = f2fma(c2, make_float2(t.x, t.y), f2mul(s2, make_float2(t.z, t.w)));
        float2 arg = f2add(l, nm);
        float wav = ex2f(arg.x);
        float wbv = ex2f(arg.y);
        if (i == 0) wa0 = wav;
        Sa += wav; Sb += wbv;
        wb[i] = wbv;
    }
    const float SaSb = Sa * Sb;

    // pass 3: dist with wa recomputed per outer-i (bit-identical rounding to pass 2)
    float dist[P];
    dist[0] = fmaf(wa0, Sb, fmaf(wb[0], Sa, -(wa0 * wb[0])));
#pragma unroll
    for (int k = 1; k < P; k++) dist[k] = 0.f;
#pragma unroll
    for (int i = 1; i < P; i++) {
        float4 t = shW[i];
        float la = fmaf(A.x, t.x, A.y * t.z);     // a-side logit (scalar)
        float wai = ex2f(la - mxa);
#pragma unroll
        for (int j = 1; j < P; j++) {
            const int k = (i * j) % P;
            dist[k] = fmaf(wai, wb[j], dist[k]);
        }
    }

    // re-encode + normalize
    float X0 = 0.f, X1 = 0.f, Y0 = 0.f, Y1 = 0.f;
#pragma unroll
    for (int k = 0; k < P; k++) {
        float2 e = shE[k];
        if (k & 1) { X1 = fmaf(dist[k], e.x, X1); Y1 = fmaf(dist[k], e.y, Y1); }
        else       { X0 = fmaf(dist[k], e.x, X0); Y0 = fmaf(dist[k], e.y, Y0); }
    }
    const float inv = rcpf(SaSb);
    oMul[idx] = make_float2((X0 + X1) * inv, (Y0 + Y1) * inv);
}

// One prime per block (blockIdx.y selects the prime) -> 20480 warps total,
// occupancy becomes register-limited only.
__global__ void __launch_bounds__(128, 7)
circle_kernel(const float* __restrict__ a, const float* __restrict__ b,
              float* __restrict__ out)
{
    __shared__ float4 shW[29];
    __shared__ float2 shE[29];

    const int y = blockIdx.y;
    // primes:   2  3  5  7  11 13 17 19 23  29
    // offsets:  0  2  5  10 17 28 41 58 77 100
    const int OFFS[M] = {0, 2, 5, 10, 17, 28, 41, 58, 77, 100};
    const int PS[M]   = {2, 3, 5, 7, 11, 13, 17, 19, 23, 29};
    const int P = PS[y], OFF = OFFS[y];
    if (threadIdx.x < P) {
        shW[threadIdx.x] = g_tabW[OFF + threadIdx.x];
        shE[threadIdx.x] = g_tabE[OFF + threadIdx.x];
    }
    __syncthreads();

    const int pos = blockIdx.x * 128 + threadIdx.x;

    const float2* a2 = (const float2*)a;
    const float2* b2 = (const float2*)b;
    float2* oAdd = (float2*)out;
    float2* oSub = oAdd + (size_t)NPOS * M;
    float2* oMul = oSub + (size_t)NPOS * M;

    switch (y) {
        case 0: prime_packed< 2, 0>(pos, a2, b2, oAdd, oSub, oMul, shW, shE); break;
        case 1: prime_packed< 3, 1>(pos, a2, b2, oAdd, oSub, oMul, shW, shE); break;
        case 2: prime_packed< 5, 2>(pos, a2, b2, oAdd, oSub, oMul, shW, shE); break;
        case 3: prime_packed< 7, 3>(pos, a2, b2, oAdd, oSub, oMul, shW, shE); break;
        case 4: prime_packed<11, 4>(pos, a2, b2, oAdd, oSub, oMul, shW, shE); break;
        case 5: prime_packed<13, 5>(pos, a2, b2, oAdd, oSub, oMul, shW, shE); break;
        case 6: prime_packed<17, 6>(pos, a2, b2, oAdd, oSub, oMul, shW, shE); break;
        case 7: prime_packed<19, 7>(pos, a2, b2, oAdd, oSub, oMul, shW, shE); break;
        case 8: prime_lowreg<23, 8>(pos, a2, b2, oAdd, oSub, oMul, shW, shE); break;
        case 9: prime_lowreg<29, 9>(pos, a2, b2, oAdd, oSub, oMul, shW, shE); break;
    }
}

extern "C" void kernel_launch(void* const* d_in, const int* in_sizes, int n_in,
                              void* d_out, int out_size) {
    const float* a = (const float*)d_in[0];
    const float* b = (const float*)d_in[1];
    float* out = (float*)d_out;
    init_tables_kernel<<<1, 160>>>();
    dim3 grid(NPOS / 128, M);
    circle_kernel<<<grid, 128>>>(a, b, out);
}